// round 7
// baseline (speedup 1.0000x reference)
#include <cuda_runtime.h>
#include <cuda_fp16.h>

#define Bb 2
#define Ls 2048
#define Dm 1024
#define Hh 16
#define Dk 64
#define Dv 64
#define BHN (Bb*Hh)

// fp16 scratch
__device__ __half g_Q[(size_t)Bb*Hh*Ls*Dk];
__device__ __half g_K[(size_t)Bb*Hh*Ls*Dk];
__device__ __half g_V[(size_t)Bb*Hh*Ls*Dv];
__device__ __half g_Z[(size_t)Bb*Ls*Hh*Dv];   // (B, L, H*Dv) head-concat

// ---- helpers --------------------------------------------------------------
__device__ __forceinline__ unsigned packh2(float lo, float hi){
    __half2 h = __floats2half2_rn(lo, hi);
    return *(unsigned*)&h;
}
__device__ __forceinline__ void mma16(float c[4], const unsigned a[4], const unsigned b[2]){
    asm volatile("mma.sync.aligned.m16n8k16.row.col.f32.f16.f16.f32 "
        "{%0,%1,%2,%3},{%4,%5,%6,%7},{%8,%9},{%0,%1,%2,%3};"
        : "+f"(c[0]),"+f"(c[1]),"+f"(c[2]),"+f"(c[3])
        : "r"(a[0]),"r"(a[1]),"r"(a[2]),"r"(a[3]),"r"(b[0]),"r"(b[1]));
}
__device__ __forceinline__ unsigned smaddr(const void* p){
    return (unsigned)__cvta_generic_to_shared(p);
}
__device__ __forceinline__ void ldsm4(unsigned* r, unsigned addr){
    asm volatile("ldmatrix.sync.aligned.m8n8.x4.shared.b16 {%0,%1,%2,%3}, [%4];"
        : "=r"(r[0]),"=r"(r[1]),"=r"(r[2]),"=r"(r[3]) : "r"(addr));
}
__device__ __forceinline__ void ldsm4t(unsigned* r, unsigned addr){
    asm volatile("ldmatrix.sync.aligned.m8n8.x4.trans.shared.b16 {%0,%1,%2,%3}, [%4];"
        : "=r"(r[0]),"=r"(r[1]),"=r"(r[2]),"=r"(r[3]) : "r"(addr));
}

// ---------------------------------------------------------------------------
// Kernel 1: QKV projections (fp32 in -> fp16 out). CTA 128m x 64n, BK=32.
// A tile [m][k] pitch 40h (80B), W tile [k][n] pitch 72h (144B) — both
// odd-16B pitches => conflict-free ldmatrix. A: x4 non-trans; B: x4.trans.
// ---------------------------------------------------------------------------
#define SAPH 40
#define SWPH 72

__global__ __launch_bounds__(256) void qkv_kernel(
    const float* __restrict__ X,
    const float* __restrict__ Wq, const float* __restrict__ bq,
    const float* __restrict__ Wk, const float* __restrict__ bk,
    const float* __restrict__ Wv, const float* __restrict__ bv)
{
    __shared__ __half sa[128 * SAPH];           // X tile [m][k]
    __shared__ __half sw[32 * SWPH];            // W tile [k][n]

    int z   = blockIdx.y;
    int sel = z / BHN;
    int bh  = z - sel * BHN;
    int b   = bh / Hh;
    int h   = bh - b * Hh;

    const float* W; const float* bias; __half* out; float osc;
    if (sel == 0)      { W = Wq; bias = bq; out = g_Q; osc = 0.125f; }
    else if (sel == 1) { W = Wk; bias = bk; out = g_K; osc = 1.0f; }
    else               { W = Wv; bias = bv; out = g_V; osc = 1.0f; }
    W    += (size_t)h * Dm * Dk;
    bias += h * Dk;
    out  += (size_t)bh * Ls * Dk + (size_t)blockIdx.x * 128 * Dk;
    const float* A = X + (size_t)b * Ls * Dm + (size_t)blockIdx.x * 128 * Dm;

    int tid = threadIdx.x, lane = tid & 31, warp = tid >> 5;
    int qr = lane >> 2, qc = lane & 3;
    int m0 = (warp & 3) * 32, n0 = (warp >> 2) * 32;

    // ldmatrix addresses (constant across kt)
    unsigned aAddr[2][2], bAddr[2][2];
#pragma unroll
    for (int mi = 0; mi < 2; mi++)
#pragma unroll
        for (int ks = 0; ks < 2; ks++)
            aAddr[mi][ks] = smaddr(&sa[(m0 + mi * 16 + (lane & 15)) * SAPH + ks * 16 + (lane >> 4) * 8]);
#pragma unroll
    for (int ks = 0; ks < 2; ks++)
#pragma unroll
        for (int hf = 0; hf < 2; hf++)
            bAddr[ks][hf] = smaddr(&sw[(ks * 16 + hf * 8 + (lane & 7)) * SWPH + n0 + (lane >> 3) * 8]);

    // W-tile thread slots: r = tid>>3 (32 rows), c8 = tid&7 (8 halfs each)
    int wr = tid >> 3, wc8 = tid & 7;

    float4 ra[4], rw0, rw1;
#pragma unroll
    for (int i = 0; i < 4; i++) {
        int id = tid + 256 * i; int r = id >> 3, c4 = id & 7;
        ra[i] = *(const float4*)(A + (size_t)r * Dm + c4 * 4);
    }
    rw0 = *(const float4*)(W + (size_t)wr * Dk + wc8 * 8);
    rw1 = *(const float4*)(W + (size_t)wr * Dk + wc8 * 8 + 4);

    float c[2][4][4] = {};

    for (int kt = 0; kt < 32; ++kt) {
        // commit staged regs to smem (fp16 rne)
#pragma unroll
        for (int i = 0; i < 4; i++) {
            int id = tid + 256 * i; int r = id >> 3, c4 = id & 7;
            unsigned lo = packh2(ra[i].x, ra[i].y);
            unsigned hi = packh2(ra[i].z, ra[i].w);
            *(uint2*)&sa[r * SAPH + c4 * 4] = make_uint2(lo, hi);
        }
        {
            uint4 wv;
            wv.x = packh2(rw0.x, rw0.y); wv.y = packh2(rw0.z, rw0.w);
            wv.z = packh2(rw1.x, rw1.y); wv.w = packh2(rw1.z, rw1.w);
            *(uint4*)&sw[wr * SWPH + wc8 * 8] = wv;
        }
        __syncthreads();
        if (kt + 1 < 32) {
#pragma unroll
            for (int i = 0; i < 4; i++) {
                int id = tid + 256 * i; int r = id >> 3, c4 = id & 7;
                ra[i] = *(const float4*)(A + (size_t)r * Dm + (kt + 1) * 32 + c4 * 4);
            }
            rw0 = *(const float4*)(W + (size_t)((kt + 1) * 32 + wr) * Dk + wc8 * 8);
            rw1 = *(const float4*)(W + (size_t)((kt + 1) * 32 + wr) * Dk + wc8 * 8 + 4);
        }
#pragma unroll
        for (int ks = 0; ks < 2; ++ks) {
            unsigned a0[4], a1[4], b0[4], b1[4];
            ldsm4(a0, aAddr[0][ks]);
            ldsm4(a1, aAddr[1][ks]);
            ldsm4t(b0, bAddr[ks][0]);
            ldsm4t(b1, bAddr[ks][1]);
#pragma unroll
            for (int nf = 0; nf < 4; nf++) {
                unsigned bb[2] = { b0[nf], b1[nf] };
                mma16(c[0][nf], a0, bb);
                mma16(c[1][nf], a1, bb);
            }
        }
        __syncthreads();
    }

#pragma unroll
    for (int mi = 0; mi < 2; mi++) {
#pragma unroll
        for (int nf = 0; nf < 4; nf++) {
            int col = n0 + nf * 8 + 2 * qc;
            float bx = bias[col], by = bias[col + 1];
            int row = m0 + mi * 16 + qr;
            *(unsigned*)(out + (size_t)row * Dk + col) =
                packh2((c[mi][nf][0] + bx) * osc, (c[mi][nf][1] + by) * osc);
            *(unsigned*)(out + (size_t)(row + 8) * Dk + col) =
                packh2((c[mi][nf][2] + bx) * osc, (c[mi][nf][3] + by) * osc);
        }
    }
}

// ---------------------------------------------------------------------------
// Kernel 2: flash attention, fp16 + ldmatrix everywhere.
// Q/K tiles [seq][dk] pitch 72h; V tile [seq][dv] pitch 72h.
// Q frags hoisted to regs; K B-frags x4 non-trans; V B-frags x4.trans.
// P packs directly into A fragments (fp16 C layout == A layout).
// ---------------------------------------------------------------------------
#define QKP 72
#define VPH 72
#define FLASH_SMEM ((3 * 128 * QKP) * (int)sizeof(__half))

__global__ __launch_bounds__(256) void flash_kernel()
{
    extern __shared__ char smraw[];
    __half* qs  = (__half*)smraw;              // [128][QKP]
    __half* ksm = qs + 128 * QKP;              // [128][QKP]
    __half* vsm = ksm + 128 * QKP;             // [128][VPH]

    int bh = blockIdx.y;
    int q0 = blockIdx.x * 128;
    const __half* Qg = g_Q + (size_t)bh * Ls * Dk + (size_t)q0 * Dk;
    const __half* Kg = g_K + (size_t)bh * Ls * Dk;
    const __half* Vg = g_V + (size_t)bh * Ls * Dv;
    int b = bh >> 4, h = bh & 15;

    int tid = threadIdx.x, lane = tid & 31, warp = tid >> 5;
    int qr = lane >> 2, qc = lane & 3;
    int m0 = warp * 16;

    // stage Q, then hoist fragments to registers
#pragma unroll
    for (int i = 0; i < 4; i++) {
        int id = tid + 256 * i; int r = id >> 3, c8 = id & 7;
        *(uint4*)&qs[r * QKP + c8 * 8] = *(const uint4*)(Qg + (size_t)r * Dk + c8 * 8);
    }
    __syncthreads();
    unsigned aq[4][4];
#pragma unroll
    for (int ks = 0; ks < 4; ++ks)
        ldsm4(aq[ks], smaddr(&qs[(m0 + (lane & 15)) * QKP + ks * 16 + (lane >> 4) * 8]));
    __syncthreads();

    // ldmatrix base addresses (constant across tiles)
    unsigned kBase = smaddr(&ksm[((lane >> 3) * 8 + (lane & 7)) * QKP]);   // rows = n
    unsigned vBase = smaddr(&vsm[(lane & 7) * VPH + (lane >> 3) * 8]);     // rows = seq (trans)

    float co[8][4] = {};
    float mA = -1e30f, mB = -1e30f, lA = 0.f, lB = 0.f;

    for (int t = 0; t < Ls / 128; ++t) {
        // K, V tile copies (plain 16B)
#pragma unroll
        for (int i = 0; i < 4; i++) {
            int id = tid + 256 * i; int r = id >> 3, c8 = id & 7;
            *(uint4*)&ksm[r * QKP + c8 * 8] =
                *(const uint4*)(Kg + (size_t)(t * 128 + r) * Dk + c8 * 8);
            *(uint4*)&vsm[r * VPH + c8 * 8] =
                *(const uint4*)(Vg + (size_t)(t * 128 + r) * Dv + c8 * 8);
        }
        __syncthreads();

        // ---- S = Q K^T : per warp 16 x 128 ----
        float sc[16][4] = {};
#pragma unroll
        for (int ks = 0; ks < 4; ++ks) {
#pragma unroll
            for (int nfg = 0; nfg < 4; nfg++) {
                unsigned b0[4], b1[4];
                unsigned base = kBase + (unsigned)(nfg * 32 * QKP * 2 + ks * 32);
                ldsm4(b0, base);
                ldsm4(b1, base + 16);
#pragma unroll
                for (int j = 0; j < 4; j++) {
                    unsigned bb[2] = { b0[j], b1[j] };
                    mma16(sc[nfg * 4 + j], aq[ks], bb);
                }
            }
        }

        // ---- online softmax in registers ----
        float mxA = -1e30f, mxB = -1e30f;
#pragma unroll
        for (int nf = 0; nf < 16; nf++) {
            mxA = fmaxf(mxA, fmaxf(sc[nf][0], sc[nf][1]));
            mxB = fmaxf(mxB, fmaxf(sc[nf][2], sc[nf][3]));
        }
        mxA = fmaxf(mxA, __shfl_xor_sync(0xffffffffu, mxA, 1));
        mxA = fmaxf(mxA, __shfl_xor_sync(0xffffffffu, mxA, 2));
        mxB = fmaxf(mxB, __shfl_xor_sync(0xffffffffu, mxB, 1));
        mxB = fmaxf(mxB, __shfl_xor_sync(0xffffffffu, mxB, 2));

        float mnA = fmaxf(mA, mxA), mnB = fmaxf(mB, mxB);
        float aAl = __expf(mA - mnA), aBl = __expf(mB - mnB);
        float sA = 0.f, sB = 0.f;
#pragma unroll
        for (int nf = 0; nf < 16; nf++) {
            float p0 = __expf(sc[nf][0] - mnA);
            float p1 = __expf(sc[nf][1] - mnA);
            float p2 = __expf(sc[nf][2] - mnB);
            float p3 = __expf(sc[nf][3] - mnB);
            sA += p0 + p1; sB += p2 + p3;
            sc[nf][0] = p0; sc[nf][1] = p1; sc[nf][2] = p2; sc[nf][3] = p3;
        }
        sA += __shfl_xor_sync(0xffffffffu, sA, 1);
        sA += __shfl_xor_sync(0xffffffffu, sA, 2);
        sB += __shfl_xor_sync(0xffffffffu, sB, 1);
        sB += __shfl_xor_sync(0xffffffffu, sB, 2);
        lA = lA * aAl + sA; mA = mnA;
        lB = lB * aBl + sB; mB = mnB;

#pragma unroll
        for (int vf = 0; vf < 8; vf++) {
            co[vf][0] *= aAl; co[vf][1] *= aAl;
            co[vf][2] *= aBl; co[vf][3] *= aBl;
        }

        // ---- O += P V : A frags packed from registers, B via trans ldmatrix ----
#pragma unroll
        for (int kk = 0; kk < 8; ++kk) {
            unsigned a[4];
            a[0] = packh2(sc[2*kk    ][0], sc[2*kk    ][1]);
            a[1] = packh2(sc[2*kk    ][2], sc[2*kk    ][3]);
            a[2] = packh2(sc[2*kk + 1][0], sc[2*kk + 1][1]);
            a[3] = packh2(sc[2*kk + 1][2], sc[2*kk + 1][3]);
#pragma unroll
            for (int vfg = 0; vfg < 2; vfg++) {
                unsigned b0[4], b1[4];
                unsigned base = vBase + (unsigned)(vfg * 64 + kk * 16 * VPH * 2);
                ldsm4t(b0, base);
                ldsm4t(b1, base + (unsigned)(8 * VPH * 2));
#pragma unroll
                for (int j = 0; j < 4; j++) {
                    unsigned bb[2] = { b0[j], b1[j] };
                    mma16(co[vfg * 4 + j], a, bb);
                }
            }
        }
        __syncthreads();
    }

    float iA = 1.0f / lA, iB = 1.0f / lB;
    __half* Zg = g_Z + ((size_t)(b * Ls + q0 + m0)) * (Hh * Dv) + h * Dv;
#pragma unroll
    for (int vf = 0; vf < 8; vf++) {
        int col = vf * 8 + 2 * qc;
        *(unsigned*)(Zg + (size_t)qr * (Hh * Dv) + col)       = packh2(co[vf][0] * iA, co[vf][1] * iA);
        *(unsigned*)(Zg + (size_t)(qr + 8) * (Hh * Dv) + col) = packh2(co[vf][2] * iB, co[vf][3] * iB);
    }
}

// ---------------------------------------------------------------------------
// Kernel 3: output projection (fp16 Z x Wo -> fp32 out). CTA 128m x 64n, BK=32.
// A [m][k] pitch 40h via x4; B = Wo tile [n][k] pitch 40h via x4 non-trans.
// ---------------------------------------------------------------------------
__global__ __launch_bounds__(256) void oproj_kernel(
    const float* __restrict__ Wo, const float* __restrict__ bo,
    float* __restrict__ out)
{
    __shared__ __half sa[128 * SAPH];
    __shared__ __half swo[64 * SAPH];
    const int N = Dm, K = Hh * Dv;

    const __half* A = g_Z + (size_t)blockIdx.x * 128 * K;
    int n0g = blockIdx.y * 64;

    int tid = threadIdx.x, lane = tid & 31, warp = tid >> 5;
    int qr = lane >> 2, qc = lane & 3;
    int m0 = (warp & 3) * 32, n0 = (warp >> 2) * 32;

    unsigned aAddr[2][2], bAddr[2][2];
#pragma unroll
    for (int mi = 0; mi < 2; mi++)
#pragma unroll
        for (int ks = 0; ks < 2; ks++)
            aAddr[mi][ks] = smaddr(&sa[(m0 + mi * 16 + (lane & 15)) * SAPH + ks * 16 + (lane >> 4) * 8]);
#pragma unroll
    for (int ks = 0; ks < 2; ks++)
#pragma unroll
        for (int hf = 0; hf < 2; hf++)
            bAddr[ks][hf] = smaddr(&swo[(n0 + (lane >> 3) * 8 + (lane & 7)) * SAPH + ks * 16 + hf * 8]);

    uint4 ra[2]; float4 rb[2];
#pragma unroll
    for (int i = 0; i < 2; i++) {
        int id = tid + 256 * i; int r = id >> 2, c8 = id & 3;
        ra[i] = *(const uint4*)(A + (size_t)r * K + c8 * 8);
    }
#pragma unroll
    for (int i = 0; i < 2; i++) {
        int id = tid + 256 * i; int r = id >> 3, c4 = id & 7;
        rb[i] = *(const float4*)(Wo + (size_t)(n0g + r) * K + c4 * 4);
    }

    float c[2][4][4] = {};

    for (int kt = 0; kt < K / 32; ++kt) {
#pragma unroll
        for (int i = 0; i < 2; i++) {
            int id = tid + 256 * i; int r = id >> 2, c8 = id & 3;
            *(uint4*)&sa[r * SAPH + c8 * 8] = ra[i];
        }
#pragma unroll
        for (int i = 0; i < 2; i++) {
            int id = tid + 256 * i; int r = id >> 3, c4 = id & 7;
            unsigned lo = packh2(rb[i].x, rb[i].y);
            unsigned hi = packh2(rb[i].z, rb[i].w);
            *(uint2*)&swo[r * SAPH + c4 * 4] = make_uint2(lo, hi);
        }
        __syncthreads();
        if (kt + 1 < K / 32) {
#pragma unroll
            for (int i = 0; i < 2; i++) {
                int id = tid + 256 * i; int r = id >> 2, c8 = id & 3;
                ra[i] = *(const uint4*)(A + (size_t)r * K + (kt + 1) * 32 + c8 * 8);
            }
#pragma unroll
            for (int i = 0; i < 2; i++) {
                int id = tid + 256 * i; int r = id >> 3, c4 = id & 7;
                rb[i] = *(const float4*)(Wo + (size_t)(n0g + r) * K + (kt + 1) * 32 + c4 * 4);
            }
        }
#pragma unroll
        for (int ks = 0; ks < 2; ++ks) {
            unsigned a0[4], a1[4], b0[4], b1[4];
            ldsm4(a0, aAddr[0][ks]);
            ldsm4(a1, aAddr[1][ks]);
            ldsm4(b0, bAddr[ks][0]);
            ldsm4(b1, bAddr[ks][1]);
#pragma unroll
            for (int nf = 0; nf < 4; nf++) {
                unsigned bb[2] = { b0[nf], b1[nf] };
                mma16(c[0][nf], a0, bb);
                mma16(c[1][nf], a1, bb);
            }
        }
        __syncthreads();
    }

#pragma unroll
    for (int mi = 0; mi < 2; mi++) {
#pragma unroll
        for (int nf = 0; nf < 4; nf++) {
            int col = n0g + n0 + nf * 8 + 2 * qc;
            float bx = bo[col], by = bo[col + 1];
            int row = blockIdx.x * 128 + m0 + mi * 16 + qr;
            *(float2*)(out + (size_t)row * N + col)       = make_float2(c[mi][nf][0] + bx, c[mi][nf][1] + by);
            *(float2*)(out + (size_t)(row + 8) * N + col) = make_float2(c[mi][nf][2] + bx, c[mi][nf][3] + by);
        }
    }
}

// ---------------------------------------------------------------------------
extern "C" void kernel_launch(void* const* d_in, const int* in_sizes, int n_in,
                              void* d_out, int out_size)
{
    const float* X  = (const float*)d_in[0];
    const float* Wq = (const float*)d_in[1];
    const float* bq = (const float*)d_in[2];
    const float* Wk = (const float*)d_in[3];
    const float* bk = (const float*)d_in[4];
    const float* Wv = (const float*)d_in[5];
    const float* bv = (const float*)d_in[6];
    const float* Wo = (const float*)d_in[7];
    const float* bo = (const float*)d_in[8];
    float* out = (float*)d_out;

    (void)in_sizes; (void)n_in; (void)out_size;

    cudaFuncSetAttribute(flash_kernel, cudaFuncAttributeMaxDynamicSharedMemorySize, FLASH_SMEM);

    qkv_kernel<<<dim3(Ls / 128, 3 * BHN), 256>>>(X, Wq, bq, Wk, bk, Wv, bv);
    flash_kernel<<<dim3(Ls / 128, BHN), 256, FLASH_SMEM>>>();
    oproj_kernel<<<dim3((Bb * Ls) / 128, Dm / 64), 256>>>(Wo, bo, out);
}